// round 16
// baseline (speedup 1.0000x reference)
#include <cuda_runtime.h>
#include <cuda_fp16.h>
#include <math.h>
#include <stdint.h>

#define N_TOK 1024
#define HDIM  2048
#define IDIM  1408
#define NEXP  8
#define ISH   2816
#define NSLOT 2048

#define BK   32
#define LDS  40                    // smem row stride in halves (padded)
#define TILE 10240                 // 128 rows * 40 halves * 2B
#define NSTG 4
#define SMEM_GEMM (NSTG * 2 * TILE)   // 81920

// ---- fp16 weight buffer offsets (elements) ----
#define OFF_EG 0ull
#define OFF_EU 23068672ull
#define OFF_ED 46137344ull
#define OFF_SG 69206016ull
#define OFF_SU 74973184ull
#define OFF_SD 80740352ull
#define W_TOTAL 86507520ull

// cvt1 segment boundaries (elements): [eg, eu, sg, su, x]
#define C1_B1 23068672ull
#define C1_B2 46137344ull
#define C1_B3 51904512ull
#define C1_B4 57671680ull
#define C1_TOT 59768832ull
// cvt2: [ed, sd]
#define C2_B1 23068672ull
#define C2_TOT 28835840ull

// ---------------- scratch (static device memory) ----------------
__device__ int   d_cnt[NEXP];
__device__ int   d_cnt2[NEXP];
__device__ int   d_off[NEXP];
__device__ int   d_sel[N_TOK * 2];
__device__ float d_selw[N_TOK * 2];
__device__ int   d_tok[NSLOT];
__device__ float d_wt[NSLOT];
__device__ __align__(16) __half d_wH[W_TOTAL];
__device__ __align__(16) __half d_xH[N_TOK * HDIM];
__device__ __align__(16) __half d_actSh[(size_t)N_TOK * ISH];
__device__ __align__(16) __half d_actRt[(size_t)NSLOT * IDIM];

// ---------------- helpers ----------------
__device__ __forceinline__ uint32_t smem_u32(const void* p) {
    return (uint32_t)__cvta_generic_to_shared(p);
}
__device__ __forceinline__ void cpa16(uint32_t dst, const void* src, uint32_t sz) {
    asm volatile("cp.async.cg.shared.global [%0], [%1], 16, %2;"
                 :: "r"(dst), "l"(src), "r"(sz));
}
__device__ __forceinline__ void cpa_commit() {
    asm volatile("cp.async.commit_group;");
}
__device__ __forceinline__ void cpa_wait2() {
    asm volatile("cp.async.wait_group 2;");
}
__device__ __forceinline__ void ldsm_x4(uint32_t& r0, uint32_t& r1,
                                        uint32_t& r2, uint32_t& r3, uint32_t a) {
    asm volatile("ldmatrix.sync.aligned.m8n8.x4.shared.b16 {%0,%1,%2,%3}, [%4];"
                 : "=r"(r0), "=r"(r1), "=r"(r2), "=r"(r3) : "r"(a));
}
__device__ __forceinline__ void mma_f16(float* c, const uint32_t* a,
                                        const uint32_t* b) {
    asm volatile(
        "mma.sync.aligned.m16n8k16.row.col.f32.f16.f16.f32 "
        "{%0,%1,%2,%3}, {%4,%5,%6,%7}, {%8,%9}, {%0,%1,%2,%3};"
        : "+f"(c[0]), "+f"(c[1]), "+f"(c[2]), "+f"(c[3])
        : "r"(a[0]), "r"(a[1]), "r"(a[2]), "r"(a[3]), "r"(b[0]), "r"(b[1]));
}
__device__ __forceinline__ uint32_t h2u(__half2 v) {
    return *reinterpret_cast<uint32_t*>(&v);
}
__device__ __forceinline__ void cvt8_store(const float* src, __half* dst) {
    float4 q0 = *(const float4*)src;
    float4 q1 = *(const float4*)(src + 4);
    __half2 h0 = __floats2half2_rn(q0.x, q0.y);
    __half2 h1 = __floats2half2_rn(q0.z, q0.w);
    __half2 h2 = __floats2half2_rn(q1.x, q1.y);
    __half2 h3 = __floats2half2_rn(q1.z, q1.w);
    *(uint4*)dst = make_uint4(h2u(h0), h2u(h1), h2u(h2), h2u(h3));
}

// ---------- cvt1: {eg, eu, sg, su, x} -> fp16, + out zero ----------
__global__ void cvt1_kernel(const float* __restrict__ eg,
                            const float* __restrict__ eu,
                            const float* __restrict__ sg,
                            const float* __restrict__ su,
                            const float* __restrict__ x,
                            __half* __restrict__ wH,
                            __half* __restrict__ xH,
                            float* __restrict__ out) {
    size_t i = (size_t)blockIdx.x * blockDim.x + threadIdx.x;
    if (i < (N_TOK * HDIM) / 4)
        ((float4*)out)[i] = make_float4(0.f, 0.f, 0.f, 0.f);
    if (i >= C1_TOT / 8) return;
    size_t e = i * 8;
    const float* src; __half* dst; size_t rel;
    if (e < C1_B1)      { src = eg; rel = e;         dst = wH + OFF_EG + rel; }
    else if (e < C1_B2) { src = eu; rel = e - C1_B1; dst = wH + OFF_EU + rel; }
    else if (e < C1_B3) { src = sg; rel = e - C1_B2; dst = wH + OFF_SG + rel; }
    else if (e < C1_B4) { src = su; rel = e - C1_B3; dst = wH + OFF_SU + rel; }
    else                { src = x;  rel = e - C1_B4; dst = xH + rel; }
    cvt8_store(src + rel, dst);
}

// ---------- cvt2: {ed, sd} -> fp16 (overlaps gu on stream 2) ----------
__global__ void cvt2_kernel(const float* __restrict__ ed,
                            const float* __restrict__ sd,
                            __half* __restrict__ wH) {
    size_t i = (size_t)blockIdx.x * blockDim.x + threadIdx.x;
    if (i >= C2_TOT / 8) return;
    size_t e = i * 8;
    const float* src; __half* dst; size_t rel;
    if (e < C2_B1) { src = ed; rel = e;         dst = wH + OFF_ED + rel; }
    else           { src = sd; rel = e - C2_B1; dst = wH + OFF_SD + rel; }
    cvt8_store(src + rel, dst);
}

// ---------------- routing kernels ----------------
__global__ void zero_cnt_kernel() {
    if (threadIdx.x < NEXP) { d_cnt[threadIdx.x] = 0; d_cnt2[threadIdx.x] = 0; }
}

__global__ void router_kernel(const float* __restrict__ x,
                              const float* __restrict__ gw) {
    int n    = blockIdx.x;
    int wid  = threadIdx.x >> 5;
    int lane = threadIdx.x & 31;
    __shared__ float logits[NEXP];
    const float* xr = x  + (size_t)n   * HDIM;
    const float* gr = gw + (size_t)wid * HDIM;
    float s = 0.f;
    for (int h = lane; h < HDIM; h += 32) s = fmaf(xr[h], gr[h], s);
    #pragma unroll
    for (int o = 16; o > 0; o >>= 1) s += __shfl_xor_sync(0xffffffffu, s, o);
    if (lane == 0) logits[wid] = s;
    __syncthreads();
    if (threadIdx.x == 0) {
        float mx = logits[0];
        #pragma unroll
        for (int e = 1; e < NEXP; ++e) mx = fmaxf(mx, logits[e]);
        float p[NEXP]; float sum = 0.f;
        #pragma unroll
        for (int e = 0; e < NEXP; ++e) { p[e] = expf(logits[e] - mx); sum += p[e]; }
        float inv = 1.f / sum;
        #pragma unroll
        for (int e = 0; e < NEXP; ++e) p[e] *= inv;
        float p1 = p[0]; int i1 = 0;
        float p2 = -1.f; int i2 = -1;
        #pragma unroll
        for (int e = 1; e < NEXP; ++e) {
            if (p[e] > p1)      { p2 = p1; i2 = i1; p1 = p[e]; i1 = e; }
            else if (p[e] > p2) { p2 = p[e]; i2 = e; }
        }
        float ws = p1 + p2 + 1e-20f;
        d_sel[n * 2]     = i1; d_selw[n * 2]     = p1 / ws;
        d_sel[n * 2 + 1] = i2; d_selw[n * 2 + 1] = p2 / ws;
        atomicAdd(&d_cnt[i1], 1);
        atomicAdd(&d_cnt[i2], 1);
    }
}

__global__ void offsets_scatter_kernel() {
    if (threadIdx.x == 0) {
        int acc = 0;
        #pragma unroll
        for (int e = 0; e < NEXP; ++e) { d_off[e] = acc; acc += d_cnt[e]; }
    }
    __syncthreads();
    for (int n = threadIdx.x; n < N_TOK; n += blockDim.x) {
        #pragma unroll
        for (int k = 0; k < 2; ++k) {
            int   e = d_sel[n * 2 + k];
            float w = d_selw[n * 2 + k];
            int pos  = atomicAdd(&d_cnt2[e], 1);
            int slot = d_off[e] + pos;
            d_tok[slot] = n;
            d_wt[slot]  = w;
        }
    }
}

// ---- fragment load macros (s = k-subgroup 0/1 inside a BK=32 chunk) ----
#define LD_BFRAG(bf, sB, s)                                                    \
    {                                                                          \
        _Pragma("unroll")                                                      \
        for (int jj = 0; jj < 4; ++jj) {                                       \
            uint32_t addr = (sB) + (uint32_t)(((wn + jj * 16 + (lane & 7)      \
                          + ((lane >> 4) & 1) * 8) * LDS                       \
                          + (s) * 16 + ((lane >> 3) & 1) * 8) * 2);            \
            ldsm_x4((bf)[2 * jj][0], (bf)[2 * jj][1],                          \
                    (bf)[2 * jj + 1][0], (bf)[2 * jj + 1][1], addr);           \
        }                                                                      \
    }
#define LD_AFRAG(af, sA, s)                                                    \
    {                                                                          \
        _Pragma("unroll")                                                      \
        for (int i = 0; i < 2; ++i) {                                          \
            uint32_t aOff = (uint32_t)(((wm + i * 16 + (lane & 15)) * LDS      \
                          + (s) * 16 + (lane >> 4) * 8) * 2);                  \
            ldsm_x4((af)[i][0], (af)[i][1], (af)[i][2], (af)[i][3],            \
                    (sA) + aOff);                                              \
        }                                                                      \
    }
#define MMA_ALL(acc, af, bf)                                                   \
    {                                                                          \
        _Pragma("unroll")                                                      \
        for (int i = 0; i < 2; ++i)                                            \
            _Pragma("unroll")                                                  \
            for (int j = 0; j < 8; ++j)                                        \
                mma_f16((acc)[i][j], (af)[i], (bf)[j]);                        \
    }
// issue one BK=32 stage of A+B into stage slot
#define ISSUE_STAGE(s0, k0)                                                    \
    {                                                                          \
        cpa16((s0) + stOff,             aP + (k0),     aSz);                   \
        cpa16((s0) + stOff + 16,        aP + (k0) + 8, aSz);                   \
        cpa16((s0) + TILE + stOff,      bP + (k0),     16);                    \
        cpa16((s0) + TILE + stOff + 16, bP + (k0) + 8, 16);                    \
    }

// ========== merged fused gate+up GEMM: z = 0..7 routed expert, z = 8 shared =====
__global__ __launch_bounds__(256, 2)
void gemm_gu_all(const __half* __restrict__ W,
                 const __half* __restrict__ A,
                 __half* __restrict__ actSh,
                 __half* __restrict__ actRt)
{
    int z = blockIdx.z;
    bool SH = (z == NEXP);
    int M, base = 0, N;
    size_t offG, offU;
    __half* act;
    if (SH) {
        M = N_TOK; N = ISH;
        offG = OFF_SG; offU = OFF_SU;
        act = actSh;
    } else {
        M = d_cnt[z]; base = d_off[z]; N = IDIM;
        size_t eo = (size_t)z * IDIM * HDIM;
        offG = OFF_EG + eo; offU = OFF_EU + eo;
        act = actRt;
    }
    int n0 = blockIdx.x * 64;
    if (n0 >= N) return;
    int m0 = blockIdx.y * 128;
    if (m0 >= M) return;

    extern __shared__ char smem[];
    uint32_t sb = smem_u32(smem);
    float* xS = (float*)smem;            // exchange region (post-loop reuse)

    int t = threadIdx.x, lane = t & 31, wid = t >> 5;

    int lr = t >> 1;
    int lc = (t & 1) * 16;
    bool av = (m0 + lr) < M;
    uint32_t aSz = av ? 16u : 0u;
    int arow = SH ? (av ? m0 + lr : 0) : (av ? d_tok[base + m0 + lr] : 0);
    const __half* aP = A + (size_t)arow * HDIM + lc;
    const __half* bP;
    if (lr < 64) bP = W + offG + (size_t)(n0 + lr) * HDIM + lc;
    else         bP = W + offU + (size_t)(n0 + lr - 64) * HDIM + lc;
    uint32_t stOff = (uint32_t)(lr * LDS + lc) * 2u;

    int wm = (wid & 3) * 32;
    int wn = (wid >> 2) * 64;            // 0 = gate half, 64 = up half
    bool isUp = wid >= 4;

    float acc[2][8][4];
    #pragma unroll
    for (int i = 0; i < 2; ++i)
        #pragma unroll
        for (int j = 0; j < 8; ++j)
            #pragma unroll
            for (int q = 0; q < 4; ++q) acc[i][j][q] = 0.f;

    const int KT = HDIM / BK;            // 64
    #pragma unroll
    for (int p = 0; p < NSTG - 1; ++p) {
        ISSUE_STAGE(sb + p * 2 * TILE, p * BK);
        cpa_commit();
    }

    uint32_t bf[2][8][2], af[2][2][4];
    // prologue: stage 0+1 ready; preload chunk0 s0 fragments
    cpa_wait2();
    __syncthreads();
    LD_BFRAG(bf[0], sb + TILE, 0);
    LD_AFRAG(af[0], sb, 0);

    for (int ch = 0; ch < KT; ++ch) {
        uint32_t cs = sb + (ch % NSTG) * 2 * TILE;
        if (ch + NSTG - 1 < KT)
            ISSUE_STAGE(sb + ((ch + NSTG - 1) % NSTG) * 2 * TILE,
                        (ch + NSTG - 1) * BK);
        cpa_commit();
        LD_BFRAG(bf[1], cs + TILE, 1);
        LD_AFRAG(af[1], cs, 1);
        MMA_ALL(acc, af[0], bf[0]);
        if (ch + 1 < KT) {
            cpa_wait2();
            __syncthreads();
            uint32_t ns = sb + ((ch + 1) % NSTG) * 2 * TILE;
            LD_BFRAG(bf[0], ns + TILE, 0);
            LD_AFRAG(af[0], ns, 0);
        }
        MMA_ALL(acc, af[1], bf[1]);
    }

    // ---- exchange: gate warps dump g; up warps combine + store ----
    __syncthreads();
    if (!isUp) {
        #pragma unroll
        for (int i = 0; i < 2; ++i)
            #pragma unroll
            for (int j = 0; j < 8; ++j) {
                int r = wm + i * 16 + (lane >> 2);
                int c = j * 8 + (lane & 3) * 2;
                *(float2*)&xS[r * 68 + c]       = make_float2(acc[i][j][0], acc[i][j][1]);
                *(float2*)&xS[(r + 8) * 68 + c] = make_float2(acc[i][j][2], acc[i][j][3]);
            }
    }
    __syncthreads();
    if (isUp) {
        #pragma unroll
        for (int i = 0; i < 2; ++i) {
            #pragma unroll
            for (int hh = 0; hh < 2; ++hh) {
                int r  = wm + i * 16 + (lane >> 2) + hh * 8;
                int mg = m0 + r;
                if (mg >= M) continue;
                size_t orow = (size_t)(SH ? mg : base + mg);
                __half* ph = act + orow * (size_t)N + n0;
                #pragma unroll
                for (int j = 0; j < 8; ++j) {
                    int c = j * 8 + (lane & 3) * 2;
                    float2 g2 = *(float2*)&xS[r * 68 + c];
                    float u0 = acc[i][j][hh * 2], u1 = acc[i][j][hh * 2 + 1];
                    float a0 = g2.x / (1.f + expf(-g2.x)) * u0;
                    float a1 = g2.y / (1.f + expf(-g2.y)) * u1;
                    *(__half2*)(ph + c) = __floats2half2_rn(a0, a1);
                }
            }
        }
    }
}

// ========== merged down GEMM: z = 0..7 routed expert, z = 8 shared ==============
__global__ __launch_bounds__(256, 2)
void gemm_dn_all(const __half* __restrict__ W,
                 const __half* __restrict__ actSh,
                 const __half* __restrict__ actRt,
                 float* __restrict__ Fout)
{
    int z = blockIdx.z;
    bool SH = (z == NEXP);
    int M, base = 0, K;
    size_t offW;
    const __half* A;
    if (SH) {
        M = N_TOK; K = ISH;
        offW = OFF_SD;
        A = actSh;
    } else {
        M = d_cnt[z]; base = d_off[z]; K = IDIM;
        offW = OFF_ED + (size_t)z * HDIM * IDIM;
        A = actRt;
    }
    int m0 = blockIdx.y * 128;
    if (m0 >= M) return;
    int n0 = blockIdx.x * 128;

    extern __shared__ char smem[];
    uint32_t sb = smem_u32(smem);

    int t = threadIdx.x, lane = t & 31, wid = t >> 5;

    int lr = t >> 1;
    int lc = (t & 1) * 16;
    bool av = (m0 + lr) < M;
    uint32_t aSz = av ? 16u : 0u;
    int arow = (SH ? 0 : base) + (av ? m0 + lr : 0);
    const __half* aP = A + (size_t)arow * K + lc;
    const __half* bP = W + offW + (size_t)(n0 + lr) * K + lc;
    uint32_t stOff = (uint32_t)(lr * LDS + lc) * 2u;

    int wm = (wid & 3) * 32;
    int wn = (wid >> 2) * 64;

    float acc[2][8][4];
    #pragma unroll
    for (int i = 0; i < 2; ++i)
        #pragma unroll
        for (int j = 0; j < 8; ++j)
            #pragma unroll
            for (int q = 0; q < 4; ++q) acc[i][j][q] = 0.f;

    int KT = K / BK;                     // 44 routed, 88 shared
    #pragma unroll
    for (int p = 0; p < NSTG - 1; ++p) {
        ISSUE_STAGE(sb + p * 2 * TILE, p * BK);
        cpa_commit();
    }

    uint32_t bf[2][8][2], af[2][2][4];
    cpa_wait2();
    __syncthreads();
    LD_BFRAG(bf[0], sb + TILE, 0);
    LD_AFRAG(af[0], sb, 0);

    for (int ch = 0; ch < KT; ++ch) {
        uint32_t cs = sb + (ch % NSTG) * 2 * TILE;
        if (ch + NSTG - 1 < KT)
            ISSUE_STAGE(sb + ((ch + NSTG - 1) % NSTG) * 2 * TILE,
                        (ch + NSTG - 1) * BK);
        cpa_commit();
        LD_BFRAG(bf[1], cs + TILE, 1);
        LD_AFRAG(af[1], cs, 1);
        MMA_ALL(acc, af[0], bf[0]);
        if (ch + 1 < KT) {
            cpa_wait2();
            __syncthreads();
            uint32_t ns = sb + ((ch + 1) % NSTG) * 2 * TILE;
            LD_BFRAG(bf[0], ns + TILE, 0);
            LD_AFRAG(af[0], ns, 0);
        }
        MMA_ALL(acc, af[1], bf[1]);
    }

    #pragma unroll
    for (int i = 0; i < 2; ++i) {
        #pragma unroll
        for (int hh = 0; hh < 2; ++hh) {
            int r  = wm + i * 16 + (lane >> 2) + hh * 8;
            int mg = m0 + r;
            if (mg >= M) continue;
            int tok;
            float w;
            if (SH) { tok = mg; w = 1.f; }
            else {
                int slot = base + mg;
                tok = d_tok[slot];
                w   = d_wt[slot];
            }
            float* op = Fout + (size_t)tok * HDIM + n0;
            #pragma unroll
            for (int j = 0; j < 8; ++j) {
                int c = wn + j * 8 + (lane & 3) * 2;
                atomicAdd(op + c,     w * acc[i][j][hh * 2]);
                atomicAdd(op + c + 1, w * acc[i][j][hh * 2 + 1]);
            }
        }
    }
}

// ---------------- launch ----------------
extern "C" void kernel_launch(void* const* d_in, const int* in_sizes, int n_in,
                              void* d_out, int out_size) {
    const float* x  = (const float*)d_in[0];
    const float* gw = (const float*)d_in[1];
    const float* eg = (const float*)d_in[2];
    const float* eu = (const float*)d_in[3];
    const float* ed = (const float*)d_in[4];
    const float* sg = (const float*)d_in[5];
    const float* su = (const float*)d_in[6];
    const float* sd = (const float*)d_in[7];
    float* out = (float*)d_out;

    __half *wH, *xH, *actSh, *actRt;
    cudaGetSymbolAddress((void**)&wH,    d_wH);
    cudaGetSymbolAddress((void**)&xH,    d_xH);
    cudaGetSymbolAddress((void**)&actSh, d_actSh);
    cudaGetSymbolAddress((void**)&actRt, d_actRt);

    static bool inited = false;
    static cudaStream_t s2;
    static cudaEvent_t evStart, evRoute, evC1, evC2;
    if (!inited) {
        cudaStreamCreateWithFlags(&s2, cudaStreamNonBlocking);
        cudaEventCreateWithFlags(&evStart, cudaEventDisableTiming);
        cudaEventCreateWithFlags(&evRoute, cudaEventDisableTiming);
        cudaEventCreateWithFlags(&evC1,    cudaEventDisableTiming);
        cudaEventCreateWithFlags(&evC2,    cudaEventDisableTiming);
        cudaFuncSetAttribute(gemm_gu_all, cudaFuncAttributeMaxDynamicSharedMemorySize, SMEM_GEMM);
        cudaFuncSetAttribute(gemm_dn_all, cudaFuncAttributeMaxDynamicSharedMemorySize, SMEM_GEMM);
        inited = true;
    }

    // fork s2 from the main (captured) stream
    cudaEventRecord(evStart, 0);
    cudaStreamWaitEvent(s2, evStart, 0);

    // s2 chain: routing (independent of cvt)
    zero_cnt_kernel<<<1, 32, 0, s2>>>();
    router_kernel<<<N_TOK, 256, 0, s2>>>(x, gw);
    offsets_scatter_kernel<<<1, 256, 0, s2>>>();
    cudaEventRecord(evRoute, s2);

    // main chain: cvt1 (weights needed by gu + x + out zero)
    {
        int n8 = (int)(C1_TOT / 8);
        cvt1_kernel<<<(n8 + 255) / 256, 256>>>(eg, eu, sg, su, x, wH, xH, out);
    }
    cudaEventRecord(evC1, 0);

    // s2: cvt2 (down weights) AFTER cvt1 -> overlaps gu (not DRAM-bound)
    cudaStreamWaitEvent(s2, evC1, 0);
    {
        int n8 = (int)(C2_TOT / 8);
        cvt2_kernel<<<(n8 + 255) / 256, 256, 0, s2>>>(ed, sd, wH);
    }
    cudaEventRecord(evC2, s2);

    // main: gu after routing; dn after cvt2
    cudaStreamWaitEvent(0, evRoute, 0);
    gemm_gu_all<<<dim3(ISH / 64, N_TOK / 128, NEXP + 1), 256, SMEM_GEMM>>>(
        wH, xH, actSh, actRt);
    cudaStreamWaitEvent(0, evC2, 0);
    gemm_dn_all<<<dim3(HDIM / 128, N_TOK / 128, NEXP + 1), 256, SMEM_GEMM>>>(
        wH, actSh, actRt, out);
}

// round 17
// speedup vs baseline: 1.0277x; 1.0277x over previous
#include <cuda_runtime.h>
#include <cuda_fp16.h>
#include <math.h>
#include <stdint.h>

#define N_TOK 1024
#define HDIM  2048
#define IDIM  1408
#define NEXP  8
#define ISH   2816
#define NSLOT 2048

#define BK   32
#define LDS  40                    // smem row stride in halves (padded)
#define TILE 10240                 // 128 rows * 40 halves * 2B
#define NSTG 4
#define SMEM_GEMM (NSTG * 2 * TILE)   // 81920

// ---- fp16 weight buffer offsets (elements) ----
#define OFF_EG 0ull
#define OFF_EU 23068672ull
#define OFF_ED 46137344ull
#define OFF_SG 69206016ull
#define OFF_SU 74973184ull
#define OFF_SD 80740352ull
#define W_TOTAL 86507520ull

// cvt_a: [sg, su, x]
#define CA_B1 5767168ull
#define CA_B2 11534336ull
#define CA_TOT 13631488ull
// cvt_b: [eg, eu]
#define CB_B1 23068672ull
#define CB_TOT 46137344ull
// cvt_sd / cvt_ed element counts
#define SD_TOT 5767168ull
#define ED_TOT 23068672ull

// ---------------- scratch (static device memory) ----------------
__device__ int   d_cnt[NEXP];
__device__ int   d_cnt2[NEXP];
__device__ int   d_off[NEXP];
__device__ int   d_sel[N_TOK * 2];
__device__ float d_selw[N_TOK * 2];
__device__ int   d_tok[NSLOT];
__device__ float d_wt[NSLOT];
__device__ __align__(16) __half d_wH[W_TOTAL];
__device__ __align__(16) __half d_xH[N_TOK * HDIM];
__device__ __align__(16) __half d_actSh[(size_t)N_TOK * ISH];
__device__ __align__(16) __half d_actRt[(size_t)NSLOT * IDIM];

// ---------------- helpers ----------------
__device__ __forceinline__ uint32_t smem_u32(const void* p) {
    return (uint32_t)__cvta_generic_to_shared(p);
}
__device__ __forceinline__ void cpa16(uint32_t dst, const void* src, uint32_t sz) {
    asm volatile("cp.async.cg.shared.global [%0], [%1], 16, %2;"
                 :: "r"(dst), "l"(src), "r"(sz));
}
__device__ __forceinline__ void cpa_commit() {
    asm volatile("cp.async.commit_group;");
}
__device__ __forceinline__ void cpa_wait2() {
    asm volatile("cp.async.wait_group 2;");
}
__device__ __forceinline__ void ldsm_x4(uint32_t& r0, uint32_t& r1,
                                        uint32_t& r2, uint32_t& r3, uint32_t a) {
    asm volatile("ldmatrix.sync.aligned.m8n8.x4.shared.b16 {%0,%1,%2,%3}, [%4];"
                 : "=r"(r0), "=r"(r1), "=r"(r2), "=r"(r3) : "r"(a));
}
__device__ __forceinline__ void mma_f16(float* c, const uint32_t* a,
                                        const uint32_t* b) {
    asm volatile(
        "mma.sync.aligned.m16n8k16.row.col.f32.f16.f16.f32 "
        "{%0,%1,%2,%3}, {%4,%5,%6,%7}, {%8,%9}, {%0,%1,%2,%3};"
        : "+f"(c[0]), "+f"(c[1]), "+f"(c[2]), "+f"(c[3])
        : "r"(a[0]), "r"(a[1]), "r"(a[2]), "r"(a[3]), "r"(b[0]), "r"(b[1]));
}
__device__ __forceinline__ uint32_t h2u(__half2 v) {
    return *reinterpret_cast<uint32_t*>(&v);
}
__device__ __forceinline__ void cvt8_store(const float* src, __half* dst) {
    float4 q0 = *(const float4*)src;
    float4 q1 = *(const float4*)(src + 4);
    __half2 h0 = __floats2half2_rn(q0.x, q0.y);
    __half2 h1 = __floats2half2_rn(q0.z, q0.w);
    __half2 h2 = __floats2half2_rn(q1.x, q1.y);
    __half2 h3 = __floats2half2_rn(q1.z, q1.w);
    *(uint4*)dst = make_uint4(h2u(h0), h2u(h1), h2u(h2), h2u(h3));
}

// ---------- cvt_a: {sg, su, x} + out zero (gates gu_sh) ----------
__global__ void cvt_a_kernel(const float* __restrict__ sg,
                             const float* __restrict__ su,
                             const float* __restrict__ x,
                             __half* __restrict__ wH,
                             __half* __restrict__ xH,
                             float* __restrict__ out) {
    size_t i = (size_t)blockIdx.x * blockDim.x + threadIdx.x;
    if (i < (N_TOK * HDIM) / 4)
        ((float4*)out)[i] = make_float4(0.f, 0.f, 0.f, 0.f);
    if (i >= CA_TOT / 8) return;
    size_t e = i * 8;
    const float* src; __half* dst; size_t rel;
    if (e < CA_B1)      { src = sg; rel = e;         dst = wH + OFF_SG + rel; }
    else if (e < CA_B2) { src = su; rel = e - CA_B1; dst = wH + OFF_SU + rel; }
    else                { src = x;  rel = e - CA_B2; dst = xH + rel; }
    cvt8_store(src + rel, dst);
}

// ---------- cvt_b: {eg, eu} (gates gu_rt) ----------
__global__ void cvt_b_kernel(const float* __restrict__ eg,
                             const float* __restrict__ eu,
                             __half* __restrict__ wH) {
    size_t i = (size_t)blockIdx.x * blockDim.x + threadIdx.x;
    if (i >= CB_TOT / 8) return;
    size_t e = i * 8;
    const float* src; __half* dst; size_t rel;
    if (e < CB_B1) { src = eg; rel = e;         dst = wH + OFF_EG + rel; }
    else           { src = eu; rel = e - CB_B1; dst = wH + OFF_EU + rel; }
    cvt8_store(src + rel, dst);
}

// ---------- cvt_sd / cvt_ed ----------
__global__ void cvt_sd_kernel(const float* __restrict__ sd, __half* __restrict__ wH) {
    size_t i = (size_t)blockIdx.x * blockDim.x + threadIdx.x;
    if (i >= SD_TOT / 8) return;
    cvt8_store(sd + i * 8, wH + OFF_SD + i * 8);
}
__global__ void cvt_ed_kernel(const float* __restrict__ ed, __half* __restrict__ wH) {
    size_t i = (size_t)blockIdx.x * blockDim.x + threadIdx.x;
    if (i >= ED_TOT / 8) return;
    cvt8_store(ed + i * 8, wH + OFF_ED + i * 8);
}

// ---------------- routing kernels ----------------
__global__ void zero_cnt_kernel() {
    if (threadIdx.x < NEXP) { d_cnt[threadIdx.x] = 0; d_cnt2[threadIdx.x] = 0; }
}

__global__ void router_kernel(const float* __restrict__ x,
                              const float* __restrict__ gw) {
    int n    = blockIdx.x;
    int wid  = threadIdx.x >> 5;
    int lane = threadIdx.x & 31;
    __shared__ float logits[NEXP];
    const float* xr = x  + (size_t)n   * HDIM;
    const float* gr = gw + (size_t)wid * HDIM;
    float s = 0.f;
    for (int h = lane; h < HDIM; h += 32) s = fmaf(xr[h], gr[h], s);
    #pragma unroll
    for (int o = 16; o > 0; o >>= 1) s += __shfl_xor_sync(0xffffffffu, s, o);
    if (lane == 0) logits[wid] = s;
    __syncthreads();
    if (threadIdx.x == 0) {
        float mx = logits[0];
        #pragma unroll
        for (int e = 1; e < NEXP; ++e) mx = fmaxf(mx, logits[e]);
        float p[NEXP]; float sum = 0.f;
        #pragma unroll
        for (int e = 0; e < NEXP; ++e) { p[e] = expf(logits[e] - mx); sum += p[e]; }
        float inv = 1.f / sum;
        #pragma unroll
        for (int e = 0; e < NEXP; ++e) p[e] *= inv;
        float p1 = p[0]; int i1 = 0;
        float p2 = -1.f; int i2 = -1;
        #pragma unroll
        for (int e = 1; e < NEXP; ++e) {
            if (p[e] > p1)      { p2 = p1; i2 = i1; p1 = p[e]; i1 = e; }
            else if (p[e] > p2) { p2 = p[e]; i2 = e; }
        }
        float ws = p1 + p2 + 1e-20f;
        d_sel[n * 2]     = i1; d_selw[n * 2]     = p1 / ws;
        d_sel[n * 2 + 1] = i2; d_selw[n * 2 + 1] = p2 / ws;
        atomicAdd(&d_cnt[i1], 1);
        atomicAdd(&d_cnt[i2], 1);
    }
}

__global__ void offsets_scatter_kernel() {
    if (threadIdx.x == 0) {
        int acc = 0;
        #pragma unroll
        for (int e = 0; e < NEXP; ++e) { d_off[e] = acc; acc += d_cnt[e]; }
    }
    __syncthreads();
    for (int n = threadIdx.x; n < N_TOK; n += blockDim.x) {
        #pragma unroll
        for (int k = 0; k < 2; ++k) {
            int   e = d_sel[n * 2 + k];
            float w = d_selw[n * 2 + k];
            int pos  = atomicAdd(&d_cnt2[e], 1);
            int slot = d_off[e] + pos;
            d_tok[slot] = n;
            d_wt[slot]  = w;
        }
    }
}

// ---- fragment load macros ----
#define LD_BFRAG(bf, sB, s)                                                    \
    {                                                                          \
        _Pragma("unroll")                                                      \
        for (int jj = 0; jj < 4; ++jj) {                                       \
            uint32_t addr = (sB) + (uint32_t)(((wn + jj * 16 + (lane & 7)      \
                          + ((lane >> 4) & 1) * 8) * LDS                       \
                          + (s) * 16 + ((lane >> 3) & 1) * 8) * 2);            \
            ldsm_x4((bf)[2 * jj][0], (bf)[2 * jj][1],                          \
                    (bf)[2 * jj + 1][0], (bf)[2 * jj + 1][1], addr);           \
        }                                                                      \
    }
#define LD_AFRAG(af, sA, s)                                                    \
    {                                                                          \
        _Pragma("unroll")                                                      \
        for (int i = 0; i < 2; ++i) {                                          \
            uint32_t aOff = (uint32_t)(((wm + i * 16 + (lane & 15)) * LDS      \
                          + (s) * 16 + (lane >> 4) * 8) * 2);                  \
            ldsm_x4((af)[i][0], (af)[i][1], (af)[i][2], (af)[i][3],            \
                    (sA) + aOff);                                              \
        }                                                                      \
    }
#define MMA_ALL(acc, af, bf)                                                   \
    {                                                                          \
        _Pragma("unroll")                                                      \
        for (int i = 0; i < 2; ++i)                                            \
            _Pragma("unroll")                                                  \
            for (int j = 0; j < 8; ++j)                                        \
                mma_f16((acc)[i][j], (af)[i], (bf)[j]);                        \
    }
#define ISSUE_STAGE(s0, k0)                                                    \
    {                                                                          \
        cpa16((s0) + stOff,             aP + (k0),     aSz);                   \
        cpa16((s0) + stOff + 16,        aP + (k0) + 8, aSz);                   \
        cpa16((s0) + TILE + stOff,      bP + (k0),     16);                    \
        cpa16((s0) + TILE + stOff + 16, bP + (k0) + 8, 16);                    \
    }

// ========== fused gate+up GEMM; z = blockIdx.z + zOff (0..7 routed, 8 shared) ===
__global__ __launch_bounds__(256, 2)
void gemm_gu_all(const __half* __restrict__ W,
                 const __half* __restrict__ A,
                 __half* __restrict__ actSh,
                 __half* __restrict__ actRt,
                 int zOff)
{
    int z = blockIdx.z + zOff;
    bool SH = (z == NEXP);
    int M, base = 0, N;
    size_t offG, offU;
    __half* act;
    if (SH) {
        M = N_TOK; N = ISH;
        offG = OFF_SG; offU = OFF_SU;
        act = actSh;
    } else {
        M = d_cnt[z]; base = d_off[z]; N = IDIM;
        size_t eo = (size_t)z * IDIM * HDIM;
        offG = OFF_EG + eo; offU = OFF_EU + eo;
        act = actRt;
    }
    int n0 = blockIdx.x * 64;
    if (n0 >= N) return;
    int m0 = blockIdx.y * 128;
    if (m0 >= M) return;

    extern __shared__ char smem[];
    uint32_t sb = smem_u32(smem);
    float* xS = (float*)smem;

    int t = threadIdx.x, lane = t & 31, wid = t >> 5;

    int lr = t >> 1;
    int lc = (t & 1) * 16;
    bool av = (m0 + lr) < M;
    uint32_t aSz = av ? 16u : 0u;
    int arow = SH ? (av ? m0 + lr : 0) : (av ? d_tok[base + m0 + lr] : 0);
    const __half* aP = A + (size_t)arow * HDIM + lc;
    const __half* bP;
    if (lr < 64) bP = W + offG + (size_t)(n0 + lr) * HDIM + lc;
    else         bP = W + offU + (size_t)(n0 + lr - 64) * HDIM + lc;
    uint32_t stOff = (uint32_t)(lr * LDS + lc) * 2u;

    int wm = (wid & 3) * 32;
    int wn = (wid >> 2) * 64;
    bool isUp = wid >= 4;

    float acc[2][8][4];
    #pragma unroll
    for (int i = 0; i < 2; ++i)
        #pragma unroll
        for (int j = 0; j < 8; ++j)
            #pragma unroll
            for (int q = 0; q < 4; ++q) acc[i][j][q] = 0.f;

    const int KT = HDIM / BK;            // 64
    #pragma unroll
    for (int p = 0; p < NSTG - 1; ++p) {
        ISSUE_STAGE(sb + p * 2 * TILE, p * BK);
        cpa_commit();
    }

    uint32_t bf[2][8][2], af[2][2][4];
    cpa_wait2();
    __syncthreads();
    LD_BFRAG(bf[0], sb + TILE, 0);
    LD_AFRAG(af[0], sb, 0);

    for (int ch = 0; ch < KT; ++ch) {
        uint32_t cs = sb + (ch % NSTG) * 2 * TILE;
        if (ch + NSTG - 1 < KT)
            ISSUE_STAGE(sb + ((ch + NSTG - 1) % NSTG) * 2 * TILE,
                        (ch + NSTG - 1) * BK);
        cpa_commit();
        LD_BFRAG(bf[1], cs + TILE, 1);
        LD_AFRAG(af[1], cs, 1);
        MMA_ALL(acc, af[0], bf[0]);
        if (ch + 1 < KT) {
            cpa_wait2();
            __syncthreads();
            uint32_t ns = sb + ((ch + 1) % NSTG) * 2 * TILE;
            LD_BFRAG(bf[0], ns + TILE, 0);
            LD_AFRAG(af[0], ns, 0);
        }
        MMA_ALL(acc, af[1], bf[1]);
    }

    __syncthreads();
    if (!isUp) {
        #pragma unroll
        for (int i = 0; i < 2; ++i)
            #pragma unroll
            for (int j = 0; j < 8; ++j) {
                int r = wm + i * 16 + (lane >> 2);
                int c = j * 8 + (lane & 3) * 2;
                *(float2*)&xS[r * 68 + c]       = make_float2(acc[i][j][0], acc[i][j][1]);
                *(float2*)&xS[(r + 8) * 68 + c] = make_float2(acc[i][j][2], acc[i][j][3]);
            }
    }
    __syncthreads();
    if (isUp) {
        #pragma unroll
        for (int i = 0; i < 2; ++i) {
            #pragma unroll
            for (int hh = 0; hh < 2; ++hh) {
                int r  = wm + i * 16 + (lane >> 2) + hh * 8;
                int mg = m0 + r;
                if (mg >= M) continue;
                size_t orow = (size_t)(SH ? mg : base + mg);
                __half* ph = act + orow * (size_t)N + n0;
                #pragma unroll
                for (int j = 0; j < 8; ++j) {
                    int c = j * 8 + (lane & 3) * 2;
                    float2 g2 = *(float2*)&xS[r * 68 + c];
                    float u0 = acc[i][j][hh * 2], u1 = acc[i][j][hh * 2 + 1];
                    float a0 = g2.x / (1.f + expf(-g2.x)) * u0;
                    float a1 = g2.y / (1.f + expf(-g2.y)) * u1;
                    *(__half2*)(ph + c) = __floats2half2_rn(a0, a1);
                }
            }
        }
    }
}

// ========== down GEMM; z = blockIdx.z + zOff ==============
__global__ __launch_bounds__(256, 2)
void gemm_dn_all(const __half* __restrict__ W,
                 const __half* __restrict__ actSh,
                 const __half* __restrict__ actRt,
                 float* __restrict__ Fout,
                 int zOff)
{
    int z = blockIdx.z + zOff;
    bool SH = (z == NEXP);
    int M, base = 0, K;
    size_t offW;
    const __half* A;
    if (SH) {
        M = N_TOK; K = ISH;
        offW = OFF_SD;
        A = actSh;
    } else {
        M = d_cnt[z]; base = d_off[z]; K = IDIM;
        offW = OFF_ED + (size_t)z * HDIM * IDIM;
        A = actRt;
    }
    int m0 = blockIdx.y * 128;
    if (m0 >= M) return;
    int n0 = blockIdx.x * 128;

    extern __shared__ char smem[];
    uint32_t sb = smem_u32(smem);

    int t = threadIdx.x, lane = t & 31, wid = t >> 5;

    int lr = t >> 1;
    int lc = (t & 1) * 16;
    bool av = (m0 + lr) < M;
    uint32_t aSz = av ? 16u : 0u;
    int arow = (SH ? 0 : base) + (av ? m0 + lr : 0);
    const __half* aP = A + (size_t)arow * K + lc;
    const __half* bP = W + offW + (size_t)(n0 + lr) * K + lc;
    uint32_t stOff = (uint32_t)(lr * LDS + lc) * 2u;

    int wm = (wid & 3) * 32;
    int wn = (wid >> 2) * 64;

    float acc[2][8][4];
    #pragma unroll
    for (int i = 0; i < 2; ++i)
        #pragma unroll
        for (int j = 0; j < 8; ++j)
            #pragma unroll
            for (int q = 0; q < 4; ++q) acc[i][j][q] = 0.f;

    int KT = K / BK;
    #pragma unroll
    for (int p = 0; p < NSTG - 1; ++p) {
        ISSUE_STAGE(sb + p * 2 * TILE, p * BK);
        cpa_commit();
    }

    uint32_t bf[2][8][2], af[2][2][4];
    cpa_wait2();
    __syncthreads();
    LD_BFRAG(bf[0], sb + TILE, 0);
    LD_AFRAG(af[0], sb, 0);

    for (int ch = 0; ch < KT; ++ch) {
        uint32_t cs = sb + (ch % NSTG) * 2 * TILE;
        if (ch + NSTG - 1 < KT)
            ISSUE_STAGE(sb + ((ch + NSTG - 1) % NSTG) * 2 * TILE,
                        (ch + NSTG - 1) * BK);
        cpa_commit();
        LD_BFRAG(bf[1], cs + TILE, 1);
        LD_AFRAG(af[1], cs, 1);
        MMA_ALL(acc, af[0], bf[0]);
        if (ch + 1 < KT) {
            cpa_wait2();
            __syncthreads();
            uint32_t ns = sb + ((ch + 1) % NSTG) * 2 * TILE;
            LD_BFRAG(bf[0], ns + TILE, 0);
            LD_AFRAG(af[0], ns, 0);
        }
        MMA_ALL(acc, af[1], bf[1]);
    }

    #pragma unroll
    for (int i = 0; i < 2; ++i) {
        #pragma unroll
        for (int hh = 0; hh < 2; ++hh) {
            int r  = wm + i * 16 + (lane >> 2) + hh * 8;
            int mg = m0 + r;
            if (mg >= M) continue;
            int tok;
            float w;
            if (SH) { tok = mg; w = 1.f; }
            else {
                int slot = base + mg;
                tok = d_tok[slot];
                w   = d_wt[slot];
            }
            float* op = Fout + (size_t)tok * HDIM + n0;
            #pragma unroll
            for (int j = 0; j < 8; ++j) {
                int c = wn + j * 8 + (lane & 3) * 2;
                atomicAdd(op + c,     w * acc[i][j][hh * 2]);
                atomicAdd(op + c + 1, w * acc[i][j][hh * 2 + 1]);
            }
        }
    }
}

// ---------------- launch ----------------
extern "C" void kernel_launch(void* const* d_in, const int* in_sizes, int n_in,
                              void* d_out, int out_size) {
    const float* x  = (const float*)d_in[0];
    const float* gw = (const float*)d_in[1];
    const float* eg = (const float*)d_in[2];
    const float* eu = (const float*)d_in[3];
    const float* ed = (const float*)d_in[4];
    const float* sg = (const float*)d_in[5];
    const float* su = (const float*)d_in[6];
    const float* sd = (const float*)d_in[7];
    float* out = (float*)d_out;

    __half *wH, *xH, *actSh, *actRt;
    cudaGetSymbolAddress((void**)&wH,    d_wH);
    cudaGetSymbolAddress((void**)&xH,    d_xH);
    cudaGetSymbolAddress((void**)&actSh, d_actSh);
    cudaGetSymbolAddress((void**)&actRt, d_actRt);

    static bool inited = false;
    static cudaStream_t s2;
    static cudaEvent_t evStart, evA, evRoute, evEd, evS2;
    if (!inited) {
        cudaStreamCreateWithFlags(&s2, cudaStreamNonBlocking);
        cudaEventCreateWithFlags(&evStart, cudaEventDisableTiming);
        cudaEventCreateWithFlags(&evA,     cudaEventDisableTiming);
        cudaEventCreateWithFlags(&evRoute, cudaEventDisableTiming);
        cudaEventCreateWithFlags(&evEd,    cudaEventDisableTiming);
        cudaEventCreateWithFlags(&evS2,    cudaEventDisableTiming);
        cudaFuncSetAttribute(gemm_gu_all, cudaFuncAttributeMaxDynamicSharedMemorySize, SMEM_GEMM);
        cudaFuncSetAttribute(gemm_dn_all, cudaFuncAttributeMaxDynamicSharedMemorySize, SMEM_GEMM);
        inited = true;
    }

    // fork s2 from the main stream
    cudaEventRecord(evStart, 0);
    cudaStreamWaitEvent(s2, evStart, 0);

    // ---- s0: cvt_a {sg, su, x} + zero(out)   (gates gu_sh) ----
    {
        int n8 = (int)(CA_TOT / 8);
        int blocks = (n8 + 255) / 256;
        int zb = (N_TOK * HDIM / 4 + 255) / 256;
        if (zb > blocks) blocks = zb;
        cvt_a_kernel<<<blocks, 256>>>(sg, su, x, wH, xH, out);
    }
    cudaEventRecord(evA, 0);

    // ---- s2: routing, then gu_sh (after cvt_a), then sd/ed cvt, then dn_sh ----
    zero_cnt_kernel<<<1, 32, 0, s2>>>();
    router_kernel<<<N_TOK, 256, 0, s2>>>(x, gw);
    offsets_scatter_kernel<<<1, 256, 0, s2>>>();
    cudaEventRecord(evRoute, s2);

    cudaStreamWaitEvent(s2, evA, 0);
    gemm_gu_all<<<dim3(ISH / 64, N_TOK / 128, 1), 256, SMEM_GEMM, s2>>>(
        wH, xH, actSh, actRt, NEXP);                      // shared gate+up
    {
        int n8 = (int)(SD_TOT / 8);
        cvt_sd_kernel<<<(n8 + 255) / 256, 256, 0, s2>>>(sd, wH);
    }
    {
        int n8 = (int)(ED_TOT / 8);
        cvt_ed_kernel<<<(n8 + 255) / 256, 256, 0, s2>>>(ed, wH);
    }
    cudaEventRecord(evEd, s2);
    gemm_dn_all<<<dim3(HDIM / 128, N_TOK / 128, 1), 256, SMEM_GEMM, s2>>>(
        wH, actSh, actRt, out, NEXP);                     // shared down
    cudaEventRecord(evS2, s2);

    // ---- s0: cvt_b {eg, eu}, then gu_rt (after route), then dn_rt (after ed) ----
    {
        int n8 = (int)(CB_TOT / 8);
        cvt_b_kernel<<<(n8 + 255) / 256, 256>>>(eg, eu, wH);
    }
    cudaStreamWaitEvent(0, evRoute, 0);
    gemm_gu_all<<<dim3(IDIM / 64, N_TOK / 128, NEXP), 256, SMEM_GEMM>>>(
        wH, xH, actSh, actRt, 0);                         // routed gate+up
    cudaStreamWaitEvent(0, evEd, 0);
    gemm_dn_all<<<dim3(HDIM / 128, N_TOK / 128, NEXP), 256, SMEM_GEMM>>>(
        wH, actSh, actRt, out, 0);                        // routed down
    cudaStreamWaitEvent(0, evS2, 0);                      // join dn_sh
}